// round 5
// baseline (speedup 1.0000x reference)
#include <cuda_runtime.h>

#define NTHREADS 256
#define PPT 2
#define PRIME_X 73856093u
#define PRIME_Y 19349663u
#define PRIME_Z 83492791u

// Table strides (floats): 16B-aligned for LDS.128 gathers.
constexpr int OFF_T0 = 0;                    // 50 x 32, stride 36
constexpr int OFF_T1 = OFF_T0 + 50 * 36;     // 200 x 16, stride 20
constexpr int OFF_T2 = OFF_T1 + 200 * 20;    // 400 x 8,  stride 12
constexpr int OFF_T3 = OFF_T2 + 400 * 12;    // 400 x 4,  stride 4
constexpr int OFF_T4 = OFF_T3 + 400 * 4;     // 400 x 3,  stride 4 (pad)
constexpr int OFF_TEND = OFF_T4 + 400 * 4;
constexpr int OFF_W1D = OFF_TEND;            // 63 x 64 (col 63 zero)
constexpr int OFF_W1C = OFF_W1D + 63 * 64;
constexpr int OFF_B1D = OFF_W1C + 63 * 64;   // 64
constexpr int OFF_B1C = OFF_B1D + 64;
constexpr int OFF_W2D = OFF_B1C + 64;        // 64 (dense col vec, zero-pad)
constexpr int OFF_W2C = OFF_W2D + 64;        // 3 x 64 (color, transposed)
constexpr int SMEM_FLOATS = OFF_W2C + 3 * 64;
constexpr int SMEM_BYTES = SMEM_FLOATS * 4;  // ~89 KB

__device__ __forceinline__ unsigned long long pk2(float a, float b) {
    unsigned long long r;
    asm("mov.b64 %0, {%1, %2};" : "=l"(r) : "f"(a), "f"(b));
    return r;
}
__device__ __forceinline__ void fma2(unsigned long long& d, unsigned long long a,
                                     unsigned long long b) {
    asm("fma.rn.f32x2 %0, %1, %2, %0;" : "+l"(d) : "l"(a), "l"(b));
}
__device__ __forceinline__ void upk2(unsigned long long v, float& a, float& b) {
    asm("mov.b64 {%0, %1}, %2;" : "=f"(a), "=f"(b) : "l"(v));
}

// ---------------- hash-grid encode (LDS.128 gathers, full unroll) -----------
template <int H, int D, int S, int BASE>
__device__ __forceinline__ void encode_level(const float* __restrict__ sT,
                                             float px, float py, float pz,
                                             float (&feat)[63]) {
    float fx = floorf(px), fy = floorf(py), fz = floorf(pz);
    float rx = px - fx, ry = py - fy, rz = pz - fz;
    int fxi = (int)fx, fyi = (int)fy, fzi = (int)fz;
    int cxi = (int)ceilf(px), cyi = (int)ceilf(py), czi = (int)ceilf(pz);

    int hx0 = (int)((unsigned)fxi * PRIME_X);
    int hx1 = (int)((unsigned)cxi * PRIME_X);
    int hy0 = (int)((unsigned)fyi * PRIME_Y);
    int hy1 = (int)((unsigned)cyi * PRIME_Y);
    int hz0 = (int)((unsigned)fzi * PRIME_Z);
    int hz1 = (int)((unsigned)czi * PRIME_Z);

    // reference quirk: FLOOR corner weighted by r, CEIL corner by (1-r)
    float wx0 = rx, wx1 = 1.0f - rx;
    float wy0 = ry, wy1 = 1.0f - ry;
    float wz0 = rz, wz1 = 1.0f - rz;

    constexpr int D4 = (D + 3) / 4;
#pragma unroll
    for (int c = 0; c < 8; c++) {
        const int bi = (c >> 2) & 1, bj = (c >> 1) & 1, bk = c & 1;
        int v = (bi ? hx1 : hx0) ^ (bj ? hy1 : hy0) ^ (bk ? hz1 : hz0);
        int h = v % H;
        if (h < 0) h += H;  // Python-style nonneg mod
        float w = (bi ? wx1 : wx0) * (bj ? wy1 : wy0) * (bk ? wz1 : wz0);
        const float4* row = (const float4*)(sT + h * S);
#pragma unroll
        for (int q = 0; q < D4; q++) {
            float4 rv = row[q];
            feat[BASE + 4 * q + 0] = fmaf(w, rv.x, feat[BASE + 4 * q + 0]);
            if (4 * q + 1 < D) feat[BASE + 4 * q + 1] = fmaf(w, rv.y, feat[BASE + 4 * q + 1]);
            if (4 * q + 2 < D) feat[BASE + 4 * q + 2] = fmaf(w, rv.z, feat[BASE + 4 * q + 2]);
            if (4 * q + 3 < D) feat[BASE + 4 * q + 3] = fmaf(w, rv.w, feat[BASE + 4 * q + 3]);
        }
    }
}

__device__ __forceinline__ void encode_all(const float* __restrict__ sm, float xv,
                                           float yv, float zv, float (&feat)[63]) {
#pragma unroll
    for (int i = 0; i < 63; i++) feat[i] = 0.0f;
    encode_level<50, 32, 36, 0>(sm + OFF_T0, xv, yv, zv, feat);
    encode_level<200, 16, 20, 32>(sm + OFF_T1, xv * 2.0f, yv * 2.0f, zv * 2.0f, feat);
    encode_level<400, 8, 12, 48>(sm + OFF_T2, xv * 4.0f, yv * 4.0f, zv * 4.0f, feat);
    encode_level<400, 4, 4, 56>(sm + OFF_T3, xv * 8.0f, yv * 8.0f, zv * 8.0f, feat);
    encode_level<400, 3, 4, 60>(sm + OFF_T4, __fdiv_rn(xv, 0.05f),
                                __fdiv_rn(yv, 0.05f), __fdiv_rn(zv, 0.05f), feat);
}

// ---------------- 2-point fused MLP head: 63 -> 63(relu) -> NO --------------
// Weight LDS shared across both points: each LDS.128 feeds 4 fma2 (2/point).
template <int NO>
__device__ __forceinline__ void mlp_head2(const float* __restrict__ sW1,
                                          const float* __restrict__ sb1,
                                          const float* __restrict__ sW2,
                                          const float (&fA)[63], const float (&fB)[63],
                                          float (&outA)[NO], float (&outB)[NO]) {
    unsigned long long oA2[NO], oB2[NO];
#pragma unroll
    for (int o = 0; o < NO; o++) { oA2[o] = pk2(0.0f, 0.0f); oB2[o] = pk2(0.0f, 0.0f); }

#pragma unroll
    for (int t = 0; t < 4; t++) {  // 4 tiles of 16 hidden units
        unsigned long long aA[8], aB[8];
#pragma unroll
        for (int c = 0; c < 8; c++) {
            const float2 b = *(const float2*)&sb1[t * 16 + 2 * c];
            unsigned long long bp = pk2(b.x, b.y);
            aA[c] = bp;
            aB[c] = bp;
        }
#pragma unroll
        for (int j = 0; j < 63; j++) {  // FULL unroll: feat stays in registers
            const unsigned long long fjA = pk2(fA[j], fA[j]);
            const unsigned long long fjB = pk2(fB[j], fB[j]);
            const ulonglong2* wp = (const ulonglong2*)&sW1[j * 64 + t * 16];
#pragma unroll
            for (int q = 0; q < 4; q++) {
                const ulonglong2 wv = wp[q];
                fma2(aA[2 * q + 0], fjA, wv.x);
                fma2(aA[2 * q + 1], fjA, wv.y);
                fma2(aB[2 * q + 0], fjB, wv.x);
                fma2(aB[2 * q + 1], fjB, wv.y);
            }
        }
        // relu + second layer (paired f32x2, shared float2 weight loads)
#pragma unroll
        for (int c = 0; c < 8; c++) {
            float a0, a1, b0, b1;
            upk2(aA[c], a0, a1);
            upk2(aB[c], b0, b1);
            const unsigned long long hA = pk2(fmaxf(a0, 0.0f), fmaxf(a1, 0.0f));
            const unsigned long long hB = pk2(fmaxf(b0, 0.0f), fmaxf(b1, 0.0f));
#pragma unroll
            for (int o = 0; o < NO; o++) {
                const float2 w2 = *(const float2*)&sW2[o * 64 + t * 16 + 2 * c];
                const unsigned long long wpk = pk2(w2.x, w2.y);
                fma2(oA2[o], hA, wpk);
                fma2(oB2[o], hB, wpk);
            }
        }
    }
#pragma unroll
    for (int o = 0; o < NO; o++) {
        float lo, hi;
        upk2(oA2[o], lo, hi);
        outA[o] += lo + hi;
        upk2(oB2[o], lo, hi);
        outB[o] += lo + hi;
    }
}

template <int H, int D, int S>
__device__ __forceinline__ void load_table(float* dst, const float* __restrict__ src,
                                           int tid) {
    for (int i = tid; i < H * D; i += NTHREADS) {
        int r = i / D, c = i - r * D;
        dst[r * S + c] = src[i];
    }
}

__global__ void __launch_bounds__(NTHREADS, 1)
nerf_fused_kernel(const float* __restrict__ x, const float* __restrict__ e0,
                  const float* __restrict__ e1, const float* __restrict__ e2,
                  const float* __restrict__ e3, const float* __restrict__ e4,
                  const float* __restrict__ Wd1, const float* __restrict__ bd1,
                  const float* __restrict__ Wd2, const float* __restrict__ bd2,
                  const float* __restrict__ Wc1, const float* __restrict__ bc1,
                  const float* __restrict__ Wc2, const float* __restrict__ bc2,
                  float* __restrict__ out, int N) {
    extern __shared__ float sm[];
    const int tid = threadIdx.x;

    load_table<50, 32, 36>(sm + OFF_T0, e0, tid);
    load_table<200, 16, 20>(sm + OFF_T1, e1, tid);
    load_table<400, 8, 12>(sm + OFF_T2, e2, tid);
    load_table<400, 4, 4>(sm + OFF_T3, e3, tid);
    load_table<400, 3, 4>(sm + OFF_T4, e4, tid);
    for (int i = tid; i < 63 * 64; i += NTHREADS) {
        int j = i >> 6, o = i & 63;
        sm[OFF_W1D + i] = (o < 63) ? Wd1[j * 63 + o] : 0.0f;
        sm[OFF_W1C + i] = (o < 63) ? Wc1[j * 63 + o] : 0.0f;
    }
    for (int i = tid; i < 64; i += NTHREADS) {
        sm[OFF_B1D + i] = (i < 63) ? bd1[i] : 0.0f;
        sm[OFF_B1C + i] = (i < 63) ? bc1[i] : 0.0f;
        sm[OFF_W2D + i] = (i < 63) ? Wd2[i] : 0.0f;
    }
    for (int i = tid; i < 3 * 64; i += NTHREADS) {
        int ch = i >> 6, o = i & 63;
        sm[OFF_W2C + i] = (o < 63) ? Wc2[o * 3 + ch] : 0.0f;
    }
    __syncthreads();

    const int iA = blockIdx.x * (NTHREADS * PPT) + tid;
    const int iB = iA + NTHREADS;
    const bool vA = iA < N, vB = iB < N;
    const int lA = vA ? iA : 0, lB = vB ? iB : 0;

    const float xA = x[lA * 3 + 0], yA = x[lA * 3 + 1], zA = x[lA * 3 + 2];
    const float xB = x[lB * 3 + 0], yB = x[lB * 3 + 1], zB = x[lB * 3 + 2];

    float fA[63], fB[63];
    encode_all(sm, xA, yA, zA, fA);
    encode_all(sm, xB, yB, zB, fB);

    float dA[1] = {bd2[0]}, dB[1] = {bd2[0]};
    mlp_head2<1>(sm + OFF_W1D, sm + OFF_B1D, sm + OFF_W2D, fA, fB, dA, dB);
    float cA[3] = {bc2[0], bc2[1], bc2[2]};
    float cB[3] = {bc2[0], bc2[1], bc2[2]};
    mlp_head2<3>(sm + OFF_W1C, sm + OFF_B1C, sm + OFF_W2C, fA, fB, cA, cB);

    if (vA) {
        out[iA] = dA[0];
        out[N + iA * 3 + 0] = cA[0];
        out[N + iA * 3 + 1] = cA[1];
        out[N + iA * 3 + 2] = cA[2];
    }
    if (vB) {
        out[iB] = dB[0];
        out[N + iB * 3 + 0] = cB[0];
        out[N + iB * 3 + 1] = cB[1];
        out[N + iB * 3 + 2] = cB[2];
    }
}

extern "C" void kernel_launch(void* const* d_in, const int* in_sizes, int n_in,
                              void* d_out, int out_size) {
    const float* x = (const float*)d_in[0];
    const float* e0 = (const float*)d_in[1];
    const float* e1 = (const float*)d_in[2];
    const float* e2 = (const float*)d_in[3];
    const float* e3 = (const float*)d_in[4];
    const float* e4 = (const float*)d_in[5];
    const float* Wd1 = (const float*)d_in[6];
    const float* bd1 = (const float*)d_in[7];
    const float* Wd2 = (const float*)d_in[8];
    const float* bd2 = (const float*)d_in[9];
    const float* Wc1 = (const float*)d_in[10];
    const float* bc1 = (const float*)d_in[11];
    const float* Wc2 = (const float*)d_in[12];
    const float* bc2 = (const float*)d_in[13];

    const int N = in_sizes[0] / 3;
    float* out = (float*)d_out;

    cudaFuncSetAttribute(nerf_fused_kernel,
                         cudaFuncAttributeMaxDynamicSharedMemorySize, SMEM_BYTES);

    const int per_block = NTHREADS * PPT;
    const int grid = (N + per_block - 1) / per_block;
    nerf_fused_kernel<<<grid, NTHREADS, SMEM_BYTES>>>(
        x, e0, e1, e2, e3, e4, Wd1, bd1, Wd2, bd2, Wc1, bc1, Wc2, bc2, out, N);
}

// round 6
// speedup vs baseline: 1.1646x; 1.1646x over previous
#include <cuda_runtime.h>

#define NTHREADS 256
#define PTS 256
#define PRIME_X 73856093u
#define PRIME_Y 19349663u
#define PRIME_Z 83492791u

// ---------------- SMEM layout (floats) ----------------
constexpr int OFF_T0 = 0;                    // 50 x 32, stride 36
constexpr int OFF_T1 = OFF_T0 + 50 * 36;     // 200 x 16, stride 20
constexpr int OFF_T2 = OFF_T1 + 200 * 20;    // 400 x 8,  stride 12
constexpr int OFF_T3 = OFF_T2 + 400 * 12;    // 400 x 4,  stride 4
constexpr int OFF_T4 = OFF_T3 + 400 * 4;     // 400 x 3,  stride 4 (pad)
constexpr int OFF_TEND = OFF_T4 + 400 * 4;   // 13800
constexpr int OFF_W1D = OFF_TEND;            // 63 x 64 (col 63 zero)
constexpr int OFF_W1C = OFF_W1D + 63 * 64;
constexpr int OFF_B1D = OFF_W1C + 63 * 64;   // 64
constexpr int OFF_B1C = OFF_B1D + 64;
constexpr int OFF_W2D = OFF_B1C + 64;        // 64
constexpr int OFF_W2C = OFF_W2D + 64;        // 3 x 64 (transposed)
constexpr int FT_STRIDE = PTS + 8;           // 264, 16B aligned, bank-shifted rows
constexpr int OFF_FT = OFF_W2C + 3 * 64;     // 63 x 264 transposed features
constexpr int SMEM_FLOATS = OFF_FT + 63 * FT_STRIDE;
constexpr int SMEM_BYTES = SMEM_FLOATS * 4;  // ~155.5 KB

__device__ __forceinline__ unsigned long long pk2(float a, float b) {
    unsigned long long r;
    asm("mov.b64 %0, {%1, %2};" : "=l"(r) : "f"(a), "f"(b));
    return r;
}
__device__ __forceinline__ void fma2(unsigned long long& d, unsigned long long a,
                                     unsigned long long b) {
    asm("fma.rn.f32x2 %0, %1, %2, %0;" : "+l"(d) : "l"(a), "l"(b));
}
__device__ __forceinline__ void upk2(unsigned long long v, float& a, float& b) {
    asm("mov.b64 {%0, %1}, %2;" : "=f"(a), "=f"(b) : "l"(v));
}

// ---------------- hash-grid encode (LDS.128 gathers, full unroll) -----------
template <int H, int D, int S, int BASE>
__device__ __forceinline__ void encode_level(const float* __restrict__ sT,
                                             float px, float py, float pz,
                                             float (&feat)[63]) {
    float fx = floorf(px), fy = floorf(py), fz = floorf(pz);
    float rx = px - fx, ry = py - fy, rz = pz - fz;
    int fxi = (int)fx, fyi = (int)fy, fzi = (int)fz;
    int cxi = (int)ceilf(px), cyi = (int)ceilf(py), czi = (int)ceilf(pz);

    int hx0 = (int)((unsigned)fxi * PRIME_X);
    int hx1 = (int)((unsigned)cxi * PRIME_X);
    int hy0 = (int)((unsigned)fyi * PRIME_Y);
    int hy1 = (int)((unsigned)cyi * PRIME_Y);
    int hz0 = (int)((unsigned)fzi * PRIME_Z);
    int hz1 = (int)((unsigned)czi * PRIME_Z);

    // reference quirk: FLOOR corner weighted by r, CEIL corner by (1-r)
    float wx0 = rx, wx1 = 1.0f - rx;
    float wy0 = ry, wy1 = 1.0f - ry;
    float wz0 = rz, wz1 = 1.0f - rz;

    constexpr int D4 = (D + 3) / 4;
#pragma unroll
    for (int c = 0; c < 8; c++) {
        const int bi = (c >> 2) & 1, bj = (c >> 1) & 1, bk = c & 1;
        int v = (bi ? hx1 : hx0) ^ (bj ? hy1 : hy0) ^ (bk ? hz1 : hz0);
        int h = v % H;
        if (h < 0) h += H;  // Python-style nonneg mod
        float w = (bi ? wx1 : wx0) * (bj ? wy1 : wy0) * (bk ? wz1 : wz0);
        const float4* row = (const float4*)(sT + h * S);
#pragma unroll
        for (int q = 0; q < D4; q++) {
            float4 rv = row[q];
            feat[BASE + 4 * q + 0] = fmaf(w, rv.x, feat[BASE + 4 * q + 0]);
            if (4 * q + 1 < D) feat[BASE + 4 * q + 1] = fmaf(w, rv.y, feat[BASE + 4 * q + 1]);
            if (4 * q + 2 < D) feat[BASE + 4 * q + 2] = fmaf(w, rv.z, feat[BASE + 4 * q + 2]);
            if (4 * q + 3 < D) feat[BASE + 4 * q + 3] = fmaf(w, rv.w, feat[BASE + 4 * q + 3]);
        }
    }
}

// ---------------- block GEMM: hidden(8p x 8c tile) = fT^T @ W1 + b1 ---------
// Each thread: pg = tid>>3 (8 points), cg = tid&7 (8 cols).
// acc[pp][c] is f32x2 over point pairs. Returns relu NOT applied.
__device__ __forceinline__ void gemm_tile(const float* __restrict__ smem,
                                          int W1_off, int B1_off, int pg, int cg,
                                          unsigned long long (&acc)[4][8]) {
    {
        const float4* b4 = (const float4*)(smem + B1_off + cg * 8);
        float4 b_lo = b4[0], b_hi = b4[1];
        float bb[8] = {b_lo.x, b_lo.y, b_lo.z, b_lo.w, b_hi.x, b_hi.y, b_hi.z, b_hi.w};
#pragma unroll
        for (int c = 0; c < 8; c++) {
            unsigned long long bp = pk2(bb[c], bb[c]);
#pragma unroll
            for (int pp = 0; pp < 4; pp++) acc[pp][c] = bp;
        }
    }
    const float4* Ap = (const float4*)(smem + OFF_FT + pg * 8);
    const float4* Bp = (const float4*)(smem + W1_off + cg * 8);
#pragma unroll 9
    for (int k = 0; k < 63; k++) {
        const float4 a_lo = Ap[k * (FT_STRIDE / 4) + 0];
        const float4 a_hi = Ap[k * (FT_STRIDE / 4) + 1];
        const float4 b_lo = Bp[k * 16 + 0];
        const float4 b_hi = Bp[k * 16 + 1];
        unsigned long long aP[4];
        aP[0] = pk2(a_lo.x, a_lo.y);
        aP[1] = pk2(a_lo.z, a_lo.w);
        aP[2] = pk2(a_hi.x, a_hi.y);
        aP[3] = pk2(a_hi.z, a_hi.w);
        float bb[8] = {b_lo.x, b_lo.y, b_lo.z, b_lo.w, b_hi.x, b_hi.y, b_hi.z, b_hi.w};
#pragma unroll
        for (int c = 0; c < 8; c++) {
            const unsigned long long b2 = pk2(bb[c], bb[c]);
            fma2(acc[0][c], aP[0], b2);
            fma2(acc[1][c], aP[1], b2);
            fma2(acc[2][c], aP[2], b2);
            fma2(acc[3][c], aP[3], b2);
        }
    }
}

template <int H, int D, int S>
__device__ __forceinline__ void load_table(float* dst, const float* __restrict__ src,
                                           int tid) {
    for (int i = tid; i < H * D; i += NTHREADS) {
        int r = i / D, c = i - r * D;
        dst[r * S + c] = src[i];
    }
}

__global__ void __launch_bounds__(NTHREADS)
nerf_fused_kernel(const float* __restrict__ x, const float* __restrict__ e0,
                  const float* __restrict__ e1, const float* __restrict__ e2,
                  const float* __restrict__ e3, const float* __restrict__ e4,
                  const float* __restrict__ Wd1, const float* __restrict__ bd1,
                  const float* __restrict__ Wd2, const float* __restrict__ bd2,
                  const float* __restrict__ Wc1, const float* __restrict__ bc1,
                  const float* __restrict__ Wc2, const float* __restrict__ bc2,
                  float* __restrict__ out, int N) {
    extern __shared__ float sm[];
    const int tid = threadIdx.x;

    // ---- cooperative SMEM fill ----
    load_table<50, 32, 36>(sm + OFF_T0, e0, tid);
    load_table<200, 16, 20>(sm + OFF_T1, e1, tid);
    load_table<400, 8, 12>(sm + OFF_T2, e2, tid);
    load_table<400, 4, 4>(sm + OFF_T3, e3, tid);
    load_table<400, 3, 4>(sm + OFF_T4, e4, tid);
    for (int i = tid; i < 63 * 64; i += NTHREADS) {
        int j = i >> 6, o = i & 63;
        sm[OFF_W1D + i] = (o < 63) ? Wd1[j * 63 + o] : 0.0f;
        sm[OFF_W1C + i] = (o < 63) ? Wc1[j * 63 + o] : 0.0f;
    }
    for (int i = tid; i < 64; i += NTHREADS) {
        sm[OFF_B1D + i] = (i < 63) ? bd1[i] : 0.0f;
        sm[OFF_B1C + i] = (i < 63) ? bc1[i] : 0.0f;
        sm[OFF_W2D + i] = (i < 63) ? Wd2[i] : 0.0f;
    }
    for (int i = tid; i < 3 * 64; i += NTHREADS) {
        int ch = i >> 6, o = i & 63;
        sm[OFF_W2C + i] = (o < 63) ? Wc2[o * 3 + ch] : 0.0f;
    }
    __syncthreads();

    // ---- phase 1: encode own point, stage transposed features ----
    const int idx = blockIdx.x * PTS + tid;
    const int lidx = (idx < N) ? idx : 0;
    const float xv = x[lidx * 3 + 0];
    const float yv = x[lidx * 3 + 1];
    const float zv = x[lidx * 3 + 2];

    float feat[63];
#pragma unroll
    for (int i = 0; i < 63; i++) feat[i] = 0.0f;
    encode_level<50, 32, 36, 0>(sm + OFF_T0, xv, yv, zv, feat);
    encode_level<200, 16, 20, 32>(sm + OFF_T1, xv * 2.0f, yv * 2.0f, zv * 2.0f, feat);
    encode_level<400, 8, 12, 48>(sm + OFF_T2, xv * 4.0f, yv * 4.0f, zv * 4.0f, feat);
    encode_level<400, 4, 4, 56>(sm + OFF_T3, xv * 8.0f, yv * 8.0f, zv * 8.0f, feat);
    encode_level<400, 3, 4, 60>(sm + OFF_T4, __fdiv_rn(xv, 0.05f),
                                __fdiv_rn(yv, 0.05f), __fdiv_rn(zv, 0.05f), feat);

#pragma unroll
    for (int k = 0; k < 63; k++) sm[OFF_FT + k * FT_STRIDE + tid] = feat[k];
    __syncthreads();

    // ---- phase 2: register-tiled GEMM heads + fused 2nd layer --------------
    const int pg = tid >> 3;   // 8-point group
    const int cg = tid & 7;    // 8-col group
    const int base_pt = blockIdx.x * PTS + pg * 8;

    // ===== head D =====
    {
        unsigned long long acc[4][8];
        gemm_tile(sm, OFF_W1D, OFF_B1D, pg, cg, acc);

        const float4* w4 = (const float4*)(sm + OFF_W2D + cg * 8);
        float4 w_lo = w4[0], w_hi = w4[1];
        float w2[8] = {w_lo.x, w_lo.y, w_lo.z, w_lo.w, w_hi.x, w_hi.y, w_hi.z, w_hi.w};

        float pd[8];
#pragma unroll
        for (int p = 0; p < 8; p++) pd[p] = 0.0f;
#pragma unroll
        for (int pp = 0; pp < 4; pp++) {
#pragma unroll
            for (int c = 0; c < 8; c++) {
                float h0, h1;
                upk2(acc[pp][c], h0, h1);
                pd[2 * pp + 0] = fmaf(fmaxf(h0, 0.0f), w2[c], pd[2 * pp + 0]);
                pd[2 * pp + 1] = fmaf(fmaxf(h1, 0.0f), w2[c], pd[2 * pp + 1]);
            }
        }
#pragma unroll
        for (int p = 0; p < 8; p++) {
            pd[p] += __shfl_xor_sync(0xffffffffu, pd[p], 1);
            pd[p] += __shfl_xor_sync(0xffffffffu, pd[p], 2);
            pd[p] += __shfl_xor_sync(0xffffffffu, pd[p], 4);
        }
        if (cg == 0) {
            const float b2 = bd2[0];
#pragma unroll
            for (int p = 0; p < 8; p++) {
                int pt = base_pt + p;
                if (pt < N) out[pt] = pd[p] + b2;
            }
        }
    }

    // ===== head C =====
    {
        unsigned long long acc[4][8];
        gemm_tile(sm, OFF_W1C, OFF_B1C, pg, cg, acc);

        float w2[3][8];
#pragma unroll
        for (int ch = 0; ch < 3; ch++) {
            const float4* w4 = (const float4*)(sm + OFF_W2C + ch * 64 + cg * 8);
            float4 w_lo = w4[0], w_hi = w4[1];
            w2[ch][0] = w_lo.x; w2[ch][1] = w_lo.y; w2[ch][2] = w_lo.z; w2[ch][3] = w_lo.w;
            w2[ch][4] = w_hi.x; w2[ch][5] = w_hi.y; w2[ch][6] = w_hi.z; w2[ch][7] = w_hi.w;
        }

        float pc[3][8];
#pragma unroll
        for (int ch = 0; ch < 3; ch++)
#pragma unroll
            for (int p = 0; p < 8; p++) pc[ch][p] = 0.0f;

#pragma unroll
        for (int pp = 0; pp < 4; pp++) {
#pragma unroll
            for (int c = 0; c < 8; c++) {
                float h0, h1;
                upk2(acc[pp][c], h0, h1);
                h0 = fmaxf(h0, 0.0f);
                h1 = fmaxf(h1, 0.0f);
#pragma unroll
                for (int ch = 0; ch < 3; ch++) {
                    pc[ch][2 * pp + 0] = fmaf(h0, w2[ch][c], pc[ch][2 * pp + 0]);
                    pc[ch][2 * pp + 1] = fmaf(h1, w2[ch][c], pc[ch][2 * pp + 1]);
                }
            }
        }
#pragma unroll
        for (int ch = 0; ch < 3; ch++)
#pragma unroll
            for (int p = 0; p < 8; p++) {
                pc[ch][p] += __shfl_xor_sync(0xffffffffu, pc[ch][p], 1);
                pc[ch][p] += __shfl_xor_sync(0xffffffffu, pc[ch][p], 2);
                pc[ch][p] += __shfl_xor_sync(0xffffffffu, pc[ch][p], 4);
            }
        if (cg == 0) {
            const float b0 = bc2[0], b1v = bc2[1], b2v = bc2[2];
#pragma unroll
            for (int p = 0; p < 8; p++) {
                int pt = base_pt + p;
                if (pt < N) {
                    out[N + pt * 3 + 0] = pc[0][p] + b0;
                    out[N + pt * 3 + 1] = pc[1][p] + b1v;
                    out[N + pt * 3 + 2] = pc[2][p] + b2v;
                }
            }
        }
    }
}

extern "C" void kernel_launch(void* const* d_in, const int* in_sizes, int n_in,
                              void* d_out, int out_size) {
    const float* x = (const float*)d_in[0];
    const float* e0 = (const float*)d_in[1];
    const float* e1 = (const float*)d_in[2];
    const float* e2 = (const float*)d_in[3];
    const float* e3 = (const float*)d_in[4];
    const float* e4 = (const float*)d_in[5];
    const float* Wd1 = (const float*)d_in[6];
    const float* bd1 = (const float*)d_in[7];
    const float* Wd2 = (const float*)d_in[8];
    const float* bd2 = (const float*)d_in[9];
    const float* Wc1 = (const float*)d_in[10];
    const float* bc1 = (const float*)d_in[11];
    const float* Wc2 = (const float*)d_in[12];
    const float* bc2 = (const float*)d_in[13];

    const int N = in_sizes[0] / 3;
    float* out = (float*)d_out;

    cudaFuncSetAttribute(nerf_fused_kernel,
                         cudaFuncAttributeMaxDynamicSharedMemorySize, SMEM_BYTES);

    const int grid = (N + PTS - 1) / PTS;
    nerf_fused_kernel<<<grid, NTHREADS, SMEM_BYTES>>>(
        x, e0, e1, e2, e3, e4, Wd1, bd1, Wd2, bd2, Wc1, bc1, Wc2, bc2, out, N);
}